// round 5
// baseline (speedup 1.0000x reference)
#include <cuda_runtime.h>
#include <math.h>

#define VV 10000
#define EE 512
#define HH 1024
#define SS 64
#define BB 64

#define SBH (SS*BB*HH)
#define BH  (BB*HH)
#define NCTA 128

// ---------------- device scratch ----------------
__device__ float g_X0[3u * SBH];
__device__ float g_H1all[SBH];
__device__ float g_h0[BH];
__device__ float g_rh0[BH];
__device__ float g_z0[BH];
__device__ float g_z1[BH];
__device__ float g_cat1[BB * 2 * HH];   // [x1, h1]
__device__ float g_cat1h[BB * 2 * HH];  // [x1, r1*h1]
__device__ int          g_bar_count;
__device__ volatile int g_bar_gen;

__device__ __forceinline__ float sigm(float x) { return 1.0f / (1.0f + __expf(-x)); }

// ---------------- grid-wide barrier (all 128 CTAs co-resident) ----------------
__device__ __forceinline__ void grid_bar() {
    __syncthreads();
    __threadfence();
    if (threadIdx.x == 0) {
        int my = g_bar_gen;
        if (atomicAdd(&g_bar_count, 1) == NCTA - 1) {
            g_bar_count = 0;
            __threadfence();
            g_bar_gen = my + 1;
        } else {
            while (g_bar_gen == my) { }
        }
    }
    __syncthreads();
}

// ---------------- init ----------------
__global__ void k_init(const float* __restrict__ h_init) {
    int i = blockIdx.x * blockDim.x + threadIdx.x;
    if (i < BH) {
        g_h0[i] = h_init[i];
        int b = i >> 10, n = i & (HH - 1);
        g_cat1[b * 2 * HH + HH + n] = h_init[BH + i];
    }
    if (i == 0) { g_bar_count = 0; }
}

// ---------------- embedding precompute GEMM (unchanged) ----------------
__global__ __launch_bounds__(256) void k_embed(
    const int* __restrict__ ids, const float* __restrict__ emb,
    const float* __restrict__ Wr, const float* __restrict__ Wz, const float* __restrict__ Wh,
    const float* __restrict__ br, const float* __restrict__ bz, const float* __restrict__ bh)
{
    const int g = blockIdx.z;
    const float* __restrict__ W    = (g == 0) ? Wr : ((g == 1) ? Wz : Wh);
    const float* __restrict__ bias = (g == 0) ? br : ((g == 1) ? bz : bh);
    float* __restrict__ out = g_X0 + (size_t)g * SBH;

    __shared__ __align__(16) float As[16][68];
    __shared__ __align__(16) float Ws[16][64];
    const int tid = threadIdx.x;
    const int bm = blockIdx.y * 64, bn = blockIdx.x * 64;
    const int lr = tid >> 2, lk = (tid & 3) * 4;
    const int wk = tid >> 4, wn = (tid & 15) * 4;
    const int tx = tid & 15, ty = tid >> 4;
    const float* __restrict__ arow = emb + (size_t)ids[bm + lr] * EE + lk;

    float acc[4][4];
#pragma unroll
    for (int i = 0; i < 4; i++)
#pragma unroll
        for (int j = 0; j < 4; j++) acc[i][j] = 0.f;

    for (int k0 = 0; k0 < EE; k0 += 16) {
        float4 av = *(const float4*)(arow + k0);
        As[lk + 0][lr] = av.x; As[lk + 1][lr] = av.y;
        As[lk + 2][lr] = av.z; As[lk + 3][lr] = av.w;
        *(float4*)&Ws[wk][wn] = *(const float4*)(W + (size_t)(k0 + wk) * HH + bn + wn);
        __syncthreads();
#pragma unroll
        for (int kk = 0; kk < 16; kk++) {
            float4 a = *(const float4*)&As[kk][ty * 4];
            float4 w = *(const float4*)&Ws[kk][tx * 4];
            acc[0][0] += a.x * w.x; acc[0][1] += a.x * w.y; acc[0][2] += a.x * w.z; acc[0][3] += a.x * w.w;
            acc[1][0] += a.y * w.x; acc[1][1] += a.y * w.y; acc[1][2] += a.y * w.z; acc[1][3] += a.y * w.w;
            acc[2][0] += a.z * w.x; acc[2][1] += a.z * w.y; acc[2][2] += a.z * w.z; acc[2][3] += a.z * w.w;
            acc[3][0] += a.w * w.x; acc[3][1] += a.w * w.y; acc[3][2] += a.w * w.z; acc[3][3] += a.w * w.w;
        }
        __syncthreads();
    }
    float4 bv = *(const float4*)(bias + bn + tx * 4);
#pragma unroll
    for (int i = 0; i < 4; i++) {
        int row = bm + ty * 4 + i;
        float* o = out + (size_t)row * HH + bn + tx * 4;
        o[0] = acc[i][0] + bv.x; o[1] = acc[i][1] + bv.y;
        o[2] = acc[i][2] + bv.z; o[3] = acc[i][3] + bv.w;
    }
}

// ---------------- k_out (unchanged) ----------------
__global__ __launch_bounds__(256) void k_out(
    const float* __restrict__ Wout, const float* __restrict__ bout,
    float* __restrict__ logits)
{
    __shared__ __align__(16) float As[16][68];
    __shared__ __align__(16) float Ws[16][64];
    const int tid = threadIdx.x;
    const int bm = blockIdx.y * 64, bn = blockIdx.x * 64;
    const int lr = tid >> 2, lk = (tid & 3) * 4;
    const int wk = tid >> 4, wn = (tid & 15) * 4;
    const int tx = tid & 15, ty = tid >> 4;
    const float* __restrict__ arow = g_H1all + (size_t)(bm + lr) * HH + lk;
    const bool wok = (bn + wn + 3) < VV;

    float acc[4][4];
#pragma unroll
    for (int i = 0; i < 4; i++)
#pragma unroll
        for (int j = 0; j < 4; j++) acc[i][j] = 0.f;

    for (int k0 = 0; k0 < HH; k0 += 16) {
        float4 av = *(const float4*)(arow + k0);
        As[lk + 0][lr] = av.x; As[lk + 1][lr] = av.y;
        As[lk + 2][lr] = av.z; As[lk + 3][lr] = av.w;
        float4 wv;
        const float* wp = Wout + (size_t)(k0 + wk) * VV;
        if (wok) {
            wv = *(const float4*)(wp + bn + wn);
        } else {
            wv.x = (bn + wn + 0 < VV) ? wp[bn + wn + 0] : 0.f;
            wv.y = (bn + wn + 1 < VV) ? wp[bn + wn + 1] : 0.f;
            wv.z = (bn + wn + 2 < VV) ? wp[bn + wn + 2] : 0.f;
            wv.w = (bn + wn + 3 < VV) ? wp[bn + wn + 3] : 0.f;
        }
        *(float4*)&Ws[wk][wn] = wv;
        __syncthreads();
#pragma unroll
        for (int kk = 0; kk < 16; kk++) {
            float4 a = *(const float4*)&As[kk][ty * 4];
            float4 w = *(const float4*)&Ws[kk][tx * 4];
            acc[0][0] += a.x * w.x; acc[0][1] += a.x * w.y; acc[0][2] += a.x * w.z; acc[0][3] += a.x * w.w;
            acc[1][0] += a.y * w.x; acc[1][1] += a.y * w.y; acc[1][2] += a.y * w.z; acc[1][3] += a.y * w.w;
            acc[2][0] += a.z * w.x; acc[2][1] += a.z * w.y; acc[2][2] += a.z * w.z; acc[2][3] += a.z * w.w;
            acc[3][0] += a.w * w.x; acc[3][1] += a.w * w.y; acc[3][2] += a.w * w.z; acc[3][3] += a.w * w.w;
        }
        __syncthreads();
    }
#pragma unroll
    for (int i = 0; i < 4; i++) {
        int row = bm + ty * 4 + i;
#pragma unroll
        for (int j = 0; j < 4; j++) {
            int col = bn + tx * 4 + j;
            if (col < VV) logits[(size_t)row * VV + col] = acc[i][j] + bout[col];
        }
    }
}

// ============ persistent-scan GEMM primitives (256 threads) ============
// Gate phase: both teams (gate = tid>>7) share one A tile; each computes its gate.
// C tile [64 x 8] per gate, double-buffered, A loaded via __ldcg (cross-CTA state).
template<int CHUNKS>
__device__ __forceinline__ void gemm_gates(
    const float* __restrict__ A, int lda,
    const float* __restrict__ W0, const float* __restrict__ W1,
    int bn, float* __restrict__ acc)
{
    __shared__ __align__(16) float As[2][32][68];
    __shared__ float Ws[2][2][32][8];   // [gate][buf]
    const int tid = threadIdx.x;
    const int gate = tid >> 7, t = tid & 127;
    const float* __restrict__ W = gate ? W1 : W0;
    const int ar = tid >> 2, akb = (tid & 3) * 8;   // A loader: 256 thr, 8 floats each
    const int wr = t >> 2,  wn  = (t & 3) * 2;      // W loader per team
    const int mg = t >> 3,  col = t & 7;            // compute map

    const float* __restrict__ Arow  = A + (size_t)ar * lda + akb;
    const float* __restrict__ Wbase = W + (size_t)wr * HH + bn + wn;

    acc[0] = acc[1] = acc[2] = acc[3] = 0.f;
    float a_st[8], w0s, w1s;

    {   // prologue chunk 0
        float4 v0 = __ldcg((const float4*)Arow);
        float4 v1 = __ldcg((const float4*)(Arow + 4));
        a_st[0]=v0.x; a_st[1]=v0.y; a_st[2]=v0.z; a_st[3]=v0.w;
        a_st[4]=v1.x; a_st[5]=v1.y; a_st[6]=v1.z; a_st[7]=v1.w;
        float2 wv = *(const float2*)Wbase;
        w0s = wv.x; w1s = wv.y;
    }
#pragma unroll
    for (int j = 0; j < 8; j++) As[0][akb + j][ar] = a_st[j];
    Ws[gate][0][wr][wn] = w0s; Ws[gate][0][wr][wn + 1] = w1s;
    __syncthreads();

    int buf = 0;
    for (int c = 0; c < CHUNKS; ++c) {
        const bool more = (c + 1 < CHUNKS);
        if (more) {
            const int k0 = (c + 1) * 32;
            float4 v0 = __ldcg((const float4*)(Arow + k0));
            float4 v1 = __ldcg((const float4*)(Arow + k0 + 4));
            a_st[0]=v0.x; a_st[1]=v0.y; a_st[2]=v0.z; a_st[3]=v0.w;
            a_st[4]=v1.x; a_st[5]=v1.y; a_st[6]=v1.z; a_st[7]=v1.w;
            float2 wv = *(const float2*)(Wbase + (size_t)k0 * HH);
            w0s = wv.x; w1s = wv.y;
        }
#pragma unroll
        for (int kk = 0; kk < 32; ++kk) {
            float4 a = *(const float4*)&As[buf][kk][mg * 4];
            float  w = Ws[gate][buf][kk][col];
            acc[0] += a.x * w; acc[1] += a.y * w;
            acc[2] += a.z * w; acc[3] += a.w * w;
        }
        if (more) {
#pragma unroll
            for (int j = 0; j < 8; j++) As[buf ^ 1][akb + j][ar] = a_st[j];
            Ws[gate][buf ^ 1][wr][wn] = w0s; Ws[gate][buf ^ 1][wr][wn + 1] = w1s;
            __syncthreads();
            buf ^= 1;
        }
    }
}

// K-split single-GEMM: team kh = tid>>7 handles K-half; team0 ends with full sums.
template<int CHUNKS>   // chunks per team = (K/2)/32
__device__ __forceinline__ void gemm_ksplit(
    const float* __restrict__ A, int lda, int khalf,
    const float* __restrict__ W, int bn, float* __restrict__ acc,
    float* __restrict__ Pp)
{
    __shared__ __align__(16) float As[2][2][32][68];   // [team][buf]
    __shared__ float Ws[2][2][32][8];
    const int tid = threadIdx.x;
    const int kh = tid >> 7, t = tid & 127;
    const int koff = kh * khalf;
    const int ar = t >> 1, akb = (t & 1) * 16;
    const int wr = t >> 2, wn  = (t & 3) * 2;
    const int mg = t >> 3, col = t & 7;

    const float* __restrict__ Arow  = A + (size_t)ar * lda + koff + akb;
    const float* __restrict__ Wbase = W + (size_t)(koff + wr) * HH + bn + wn;

    acc[0] = acc[1] = acc[2] = acc[3] = 0.f;
    float a_st[16], w0s, w1s;

    {   // prologue
#pragma unroll
        for (int j = 0; j < 4; j++) {
            float4 v = __ldcg((const float4*)(Arow + j * 4));
            a_st[j*4+0]=v.x; a_st[j*4+1]=v.y; a_st[j*4+2]=v.z; a_st[j*4+3]=v.w;
        }
        float2 wv = *(const float2*)Wbase;
        w0s = wv.x; w1s = wv.y;
    }
#pragma unroll
    for (int j = 0; j < 16; j++) As[kh][0][akb + j][ar] = a_st[j];
    Ws[kh][0][wr][wn] = w0s; Ws[kh][0][wr][wn + 1] = w1s;
    __syncthreads();

    int buf = 0;
    for (int c = 0; c < CHUNKS; ++c) {
        const bool more = (c + 1 < CHUNKS);
        if (more) {
            const int k0 = (c + 1) * 32;
#pragma unroll
            for (int j = 0; j < 4; j++) {
                float4 v = __ldcg((const float4*)(Arow + k0 + j * 4));
                a_st[j*4+0]=v.x; a_st[j*4+1]=v.y; a_st[j*4+2]=v.z; a_st[j*4+3]=v.w;
            }
            float2 wv = *(const float2*)(Wbase + (size_t)k0 * HH);
            w0s = wv.x; w1s = wv.y;
        }
#pragma unroll
        for (int kk = 0; kk < 32; ++kk) {
            float4 a = *(const float4*)&As[kh][buf][kk][mg * 4];
            float  w = Ws[kh][buf][kk][col];
            acc[0] += a.x * w; acc[1] += a.y * w;
            acc[2] += a.z * w; acc[3] += a.w * w;
        }
        if (more) {
#pragma unroll
            for (int j = 0; j < 16; j++) As[kh][buf ^ 1][akb + j][ar] = a_st[j];
            Ws[kh][buf ^ 1][wr][wn] = w0s; Ws[kh][buf ^ 1][wr][wn + 1] = w1s;
            __syncthreads();
            buf ^= 1;
        }
    }
    // reduce partials: team1 -> smem, team0 accumulates
    if (kh == 1) {
        Pp[t * 4 + 0] = acc[0]; Pp[t * 4 + 1] = acc[1];
        Pp[t * 4 + 2] = acc[2]; Pp[t * 4 + 3] = acc[3];
    }
    __syncthreads();
    if (kh == 0) {
        acc[0] += Pp[t * 4 + 0]; acc[1] += Pp[t * 4 + 1];
        acc[2] += Pp[t * 4 + 2]; acc[3] += Pp[t * 4 + 3];
    }
}

// ---------------- persistent scan kernel: the whole 64-step recurrence ----------------
__global__ __launch_bounds__(256, 1) void k_scan(
    const float* __restrict__ Wr0, const float* __restrict__ Wz0, const float* __restrict__ Wh0,
    const float* __restrict__ Wr1, const float* __restrict__ Wz1, const float* __restrict__ Wh1,
    const float* __restrict__ br1, const float* __restrict__ bz1, const float* __restrict__ bh1,
    const float* __restrict__ Wfc, const float* __restrict__ bfc)
{
    __shared__ float Pp[512];
    const int bn = blockIdx.x * 8;
    const int tid = threadIdx.x;
    const int gate = tid >> 7, t = tid & 127;
    const int mg = t >> 3, col = t & 7;

    for (int ts = 0; ts < SS; ++ts) {
        float acc[4];

        // ---- phase g0: r0 (team0) / z0 (team1) = sigm(X0[g][ts] + h0 @ W[E:]) ----
        gemm_gates<32>(g_h0, HH, Wr0 + (size_t)EE * HH, Wz0 + (size_t)EE * HH, bn, acc);
        {
            const float* X = g_X0 + (size_t)gate * SBH + (size_t)ts * BH;
#pragma unroll
            for (int i = 0; i < 4; i++) {
                int idx = (mg * 4 + i) * HH + bn + col;
                float v = sigm(acc[i] + X[idx]);
                if (gate == 0) g_rh0[idx] = v * __ldcg(&g_h0[idx]);
                else           g_z0[idx] = v;
            }
        }
        grid_bar();

        // ---- phase c0: hh0 = sigm(X0[2][ts] + rh0 @ Wh0[E:]); h0 update ----
        gemm_ksplit<16>(g_rh0, HH, 512, Wh0 + (size_t)EE * HH, bn, acc, Pp);
        if (gate == 0) {
            const float* X = g_X0 + 2ull * SBH + (size_t)ts * BH;
#pragma unroll
            for (int i = 0; i < 4; i++) {
                int idx = (mg * 4 + i) * HH + bn + col;
                float hh = sigm(acc[i] + X[idx]);
                float h = __ldcg(&g_h0[idx]);
                float z = __ldcg(&g_z0[idx]);
                g_h0[idx] = (1.f - z) * h + z * hh;
            }
        }
        grid_bar();

        // ---- phase fc: x1 = sigm(h0 @ Wfc + bfc) ----
        gemm_ksplit<16>(g_h0, HH, 512, Wfc, bn, acc, Pp);
        if (gate == 0) {
#pragma unroll
            for (int i = 0; i < 4; i++) {
                int b = mg * 4 + i, n = bn + col;
                float x1 = sigm(acc[i] + bfc[n]);
                g_cat1[b * 2 * HH + n]  = x1;
                g_cat1h[b * 2 * HH + n] = x1;
            }
        }
        grid_bar();

        // ---- phase g1: r1 (team0) / z1 (team1) over [x1, h1], K=2048 ----
        gemm_gates<64>(g_cat1, 2 * HH, Wr1, Wz1, bn, acc);
        {
#pragma unroll
            for (int i = 0; i < 4; i++) {
                int b = mg * 4 + i, n = bn + col;
                if (gate == 0) {
                    float v = sigm(acc[i] + br1[n]);
                    g_cat1h[b * 2 * HH + HH + n] = v * __ldcg(&g_cat1[b * 2 * HH + HH + n]);
                } else {
                    g_z1[b * HH + n] = sigm(acc[i] + bz1[n]);
                }
            }
        }
        grid_bar();

        // ---- phase c1: hh1 over [x1, r1*h1], K=2048; h1 update + H1all store ----
        gemm_ksplit<32>(g_cat1h, 2 * HH, 1024, Wh1, bn, acc, Pp);
        if (gate == 0) {
#pragma unroll
            for (int i = 0; i < 4; i++) {
                int b = mg * 4 + i, n = bn + col;
                float hh = sigm(acc[i] + bh1[n]);
                float h1 = __ldcg(&g_cat1[b * 2 * HH + HH + n]);
                float z  = __ldcg(&g_z1[b * HH + n]);
                float hn = (1.f - z) * h1 + z * hh;
                g_cat1[b * 2 * HH + HH + n] = hn;
                g_H1all[(size_t)ts * BH + b * HH + n] = hn;
            }
        }
        grid_bar();
    }
}

// ---------------- h_final ----------------
__global__ void k_hfinal(float* __restrict__ out) {
    int i = blockIdx.x * blockDim.x + threadIdx.x;
    if (i < BH) {
        out[i] = g_h0[i];
        int b = i >> 10, n = i & (HH - 1);
        out[BH + i] = g_cat1[b * 2 * HH + HH + n];
    }
}

extern "C" void kernel_launch(void* const* d_in, const int* in_sizes, int n_in,
                              void* d_out, int out_size)
{
    const int*   ids    = (const int*)d_in[0];
    const float* h_init = (const float*)d_in[1];
    const float* emb    = (const float*)d_in[2];
    const float* Wr0 = (const float*)d_in[3],  *Wz0 = (const float*)d_in[4],  *Wh0 = (const float*)d_in[5];
    const float* br0 = (const float*)d_in[6],  *bz0 = (const float*)d_in[7],  *bh0 = (const float*)d_in[8];
    const float* Wr1 = (const float*)d_in[9],  *Wz1 = (const float*)d_in[10], *Wh1 = (const float*)d_in[11];
    const float* br1 = (const float*)d_in[12], *bz1 = (const float*)d_in[13], *bh1 = (const float*)d_in[14];
    const float* Wfc = (const float*)d_in[15], *bfc = (const float*)d_in[16];
    const float* Wout = (const float*)d_in[17], *bout = (const float*)d_in[18];
    float* out = (float*)d_out;

    k_init<<<(BH + 255) / 256, 256>>>(h_init);
    k_embed<<<dim3(HH / 64, (SS * BB) / 64, 3), 256>>>(ids, emb, Wr0, Wz0, Wh0, br0, bz0, bh0);

    k_scan<<<NCTA, 256>>>(Wr0, Wz0, Wh0, Wr1, Wz1, Wh1, br1, bz1, bh1, Wfc, bfc);

    k_out<<<dim3((VV + 63) / 64, (SS * BB) / 64), 256>>>(Wout, bout, out);
    k_hfinal<<<(BH + 255) / 256, 256>>>(out + (size_t)SS * BB * VV);
}

// round 6
// speedup vs baseline: 1.4629x; 1.4629x over previous
#include <cuda_runtime.h>
#include <math.h>

#define VV 10000
#define EE 512
#define HH 1024
#define SS 64
#define BB 64

#define SBH (SS*BB*HH)
#define BH  (BB*HH)

typedef unsigned long long ull;

// ---------------- device scratch ----------------
__device__ float g_X0[3u * SBH];
__device__ float g_H1all[SBH];
__device__ float g_h0[BH];
__device__ float g_rh0[BH];
__device__ float g_z0[BH];
__device__ float g_z1[BH];
__device__ float g_cat1[BB * 2 * HH];   // [x1, h1]
__device__ float g_cat1h[BB * 2 * HH];  // [x1, r1*h1]

__device__ __forceinline__ float sigm(float x) { return 1.0f / (1.0f + __expf(-x)); }

// ---------------- packed f32x2 helpers (sm_103a FFMA2) ----------------
__device__ __forceinline__ ull pk2(float lo, float hi) {
    ull r; asm("mov.b64 %0, {%1, %2};" : "=l"(r) : "f"(lo), "f"(hi)); return r;
}
__device__ __forceinline__ void fma2(ull &c, ull a, ull b) {
    asm("fma.rn.f32x2 %0, %1, %2, %0;" : "+l"(c) : "l"(a), "l"(b));
}
__device__ __forceinline__ void add2(ull &c, ull a) {
    asm("add.rn.f32x2 %0, %0, %1;" : "+l"(c) : "l"(a));
}
__device__ __forceinline__ void unpk(ull v, float &lo, float &hi) {
    asm("mov.b64 {%0, %1}, %2;" : "=f"(lo), "=f"(hi) : "l"(v));
}

// ---------------- init ----------------
__global__ void k_init(const float* __restrict__ h_init) {
    int i = blockIdx.x * blockDim.x + threadIdx.x;
    if (i < BH) {
        g_h0[i] = h_init[i];
        int b = i >> 10, n = i & (HH - 1);
        g_cat1[b * 2 * HH + HH + n] = h_init[BH + i];
    }
}

// ---------------- embedding precompute GEMM (64x64x16, packed fma2) ----------------
__global__ __launch_bounds__(256) void k_embed(
    const int* __restrict__ ids, const float* __restrict__ emb,
    const float* __restrict__ Wr, const float* __restrict__ Wz, const float* __restrict__ Wh,
    const float* __restrict__ br, const float* __restrict__ bz, const float* __restrict__ bh)
{
    const int g = blockIdx.z;
    const float* __restrict__ W    = (g == 0) ? Wr : ((g == 1) ? Wz : Wh);
    const float* __restrict__ bias = (g == 0) ? br : ((g == 1) ? bz : bh);
    float* __restrict__ out = g_X0 + (size_t)g * SBH;

    __shared__ __align__(16) float As[16][68];
    __shared__ __align__(16) float Ws[16][64];
    const int tid = threadIdx.x;
    const int bm = blockIdx.y * 64, bn = blockIdx.x * 64;
    const int lr = tid >> 2, lk = (tid & 3) * 4;
    const int wk = tid >> 4, wn = (tid & 15) * 4;
    const int tx = tid & 15, ty = tid >> 4;
    const float* __restrict__ arow = emb + (size_t)ids[bm + lr] * EE + lk;

    ull accp[4][2];
#pragma unroll
    for (int i = 0; i < 4; i++) { accp[i][0] = 0ull; accp[i][1] = 0ull; }

    for (int k0 = 0; k0 < EE; k0 += 16) {
        float4 av = *(const float4*)(arow + k0);
        As[lk + 0][lr] = av.x; As[lk + 1][lr] = av.y;
        As[lk + 2][lr] = av.z; As[lk + 3][lr] = av.w;
        *(float4*)&Ws[wk][wn] = *(const float4*)(W + (size_t)(k0 + wk) * HH + bn + wn);
        __syncthreads();
#pragma unroll
        for (int kk = 0; kk < 16; kk++) {
            float4 a = *(const float4*)&As[kk][ty * 4];
            float4 w = *(const float4*)&Ws[kk][tx * 4];
            ulonglong2 wp = *reinterpret_cast<ulonglong2*>(&w);
            ull a0 = pk2(a.x, a.x), a1 = pk2(a.y, a.y);
            ull a2 = pk2(a.z, a.z), a3 = pk2(a.w, a.w);
            fma2(accp[0][0], a0, wp.x); fma2(accp[0][1], a0, wp.y);
            fma2(accp[1][0], a1, wp.x); fma2(accp[1][1], a1, wp.y);
            fma2(accp[2][0], a2, wp.x); fma2(accp[2][1], a2, wp.y);
            fma2(accp[3][0], a3, wp.x); fma2(accp[3][1], a3, wp.y);
        }
        __syncthreads();
    }
    float4 bv = *(const float4*)(bias + bn + tx * 4);
#pragma unroll
    for (int i = 0; i < 4; i++) {
        float c0, c1, c2, c3;
        unpk(accp[i][0], c0, c1); unpk(accp[i][1], c2, c3);
        int row = bm + ty * 4 + i;
        float* o = out + (size_t)row * HH + bn + tx * 4;
        o[0] = c0 + bv.x; o[1] = c1 + bv.y; o[2] = c2 + bv.z; o[3] = c3 + bv.w;
    }
}

// ---------------- k_out: logits = H1all @ Wout + bout (packed fma2) ----------------
__global__ __launch_bounds__(256) void k_out(
    const float* __restrict__ Wout, const float* __restrict__ bout,
    float* __restrict__ logits)
{
    __shared__ __align__(16) float As[16][68];
    __shared__ __align__(16) float Ws[16][64];
    const int tid = threadIdx.x;
    const int bm = blockIdx.y * 64, bn = blockIdx.x * 64;
    const int lr = tid >> 2, lk = (tid & 3) * 4;
    const int wk = tid >> 4, wn = (tid & 15) * 4;
    const int tx = tid & 15, ty = tid >> 4;
    const float* __restrict__ arow = g_H1all + (size_t)(bm + lr) * HH + lk;
    const bool wok = (bn + wn + 3) < VV;

    ull accp[4][2];
#pragma unroll
    for (int i = 0; i < 4; i++) { accp[i][0] = 0ull; accp[i][1] = 0ull; }

    for (int k0 = 0; k0 < HH; k0 += 16) {
        float4 av = *(const float4*)(arow + k0);
        As[lk + 0][lr] = av.x; As[lk + 1][lr] = av.y;
        As[lk + 2][lr] = av.z; As[lk + 3][lr] = av.w;
        float4 wv;
        const float* wp = Wout + (size_t)(k0 + wk) * VV;
        if (wok) {
            wv = *(const float4*)(wp + bn + wn);
        } else {
            wv.x = (bn + wn + 0 < VV) ? wp[bn + wn + 0] : 0.f;
            wv.y = (bn + wn + 1 < VV) ? wp[bn + wn + 1] : 0.f;
            wv.z = (bn + wn + 2 < VV) ? wp[bn + wn + 2] : 0.f;
            wv.w = (bn + wn + 3 < VV) ? wp[bn + wn + 3] : 0.f;
        }
        *(float4*)&Ws[wk][wn] = wv;
        __syncthreads();
#pragma unroll
        for (int kk = 0; kk < 16; kk++) {
            float4 a = *(const float4*)&As[kk][ty * 4];
            float4 w = *(const float4*)&Ws[kk][tx * 4];
            ulonglong2 wpk = *reinterpret_cast<ulonglong2*>(&w);
            ull a0 = pk2(a.x, a.x), a1 = pk2(a.y, a.y);
            ull a2 = pk2(a.z, a.z), a3 = pk2(a.w, a.w);
            fma2(accp[0][0], a0, wpk.x); fma2(accp[0][1], a0, wpk.y);
            fma2(accp[1][0], a1, wpk.x); fma2(accp[1][1], a1, wpk.y);
            fma2(accp[2][0], a2, wpk.x); fma2(accp[2][1], a2, wpk.y);
            fma2(accp[3][0], a3, wpk.x); fma2(accp[3][1], a3, wpk.y);
        }
        __syncthreads();
    }
#pragma unroll
    for (int i = 0; i < 4; i++) {
        float c[4];
        unpk(accp[i][0], c[0], c[1]); unpk(accp[i][1], c[2], c[3]);
        int row = bm + ty * 4 + i;
#pragma unroll
        for (int j = 0; j < 4; j++) {
            int col = bn + tx * 4 + j;
            if (col < VV) logits[(size_t)row * VV + col] = c[j] + bout[col];
        }
    }
}

// ============ step GEMM core: 256 threads, K-split x2 teams, double-buffered,
// packed FFMA2 with pre-duplicated W in smem ============
// C tile: [64 x BN] (BN=8: 4 outputs/thread on team0; BN=16: 8).
// Dynamic smem layout (floats):
//   As  [2 teams][2 buf][32 k][68]          : 8704 floats
//   Ws  [2 teams][2 buf][32 k][2*BN dup]    : 256*BN floats
//   Pp  (reduction)                         : 128*(BN/2) floats
#define AS_FLOATS 8704

template<int BN, int CHUNKS>
__device__ __forceinline__ void team_gemm(
    const float* __restrict__ A, int lda,
    const float* __restrict__ W,   // gate-offset W base, row stride HH
    int bn, ull* __restrict__ accp)
{
    extern __shared__ float dyn[];
    constexpr int WROW = 2 * BN;             // dup floats per k-row
    constexpr int NW   = BN / 4;             // W floats loaded per thread per chunk
    constexpr int NA   = BN / 4;             // packed accumulators (BN8:2, BN16:4)
    float* As = dyn;
    float* Ws = dyn + AS_FLOATS;

    const int tid = threadIdx.x;
    const int kh = tid >> 7, t = tid & 127;
    const int koff = kh * CHUNKS * 32;
    const int ar = t >> 1, akb = (t & 1) * 16;
    const int wr = t >> 2, wq = (t & 3) * NW;
    const int mg = t >> 3, col = t & 7;

    const float* __restrict__ Arow  = A + (size_t)ar * lda + koff + akb;
    const float* __restrict__ Wbase = W + (size_t)(koff + wr) * HH + bn + wq;

#pragma unroll
    for (int i = 0; i < NA; i++) accp[i] = 0ull;

    float a_st[16], w_st[NW];

    // prologue: chunk 0
#pragma unroll
    for (int j = 0; j < 4; j++) {
        float4 v = *(const float4*)(Arow + j * 4);
        a_st[j*4+0]=v.x; a_st[j*4+1]=v.y; a_st[j*4+2]=v.z; a_st[j*4+3]=v.w;
    }
    if (NW == 4) {
        float4 v = *(const float4*)(Wbase);
        w_st[0]=v.x; w_st[1]=v.y; w_st[2]=v.z; w_st[3]=v.w;
    } else {
        float2 v = *(const float2*)(Wbase);
        w_st[0]=v.x; w_st[1]=v.y;
    }
    {
        int asb = (kh * 2 + 0) * 32 * 68;
        int wsb = (kh * 2 + 0) * 32 * WROW + wr * WROW;
#pragma unroll
        for (int j = 0; j < 16; j++) As[asb + (akb + j) * 68 + ar] = a_st[j];
#pragma unroll
        for (int j = 0; j < NW; j++) {
            Ws[wsb + (wq + j) * 2 + 0] = w_st[j];
            Ws[wsb + (wq + j) * 2 + 1] = w_st[j];
        }
    }
    __syncthreads();

    int buf = 0;
    for (int c = 0; c < CHUNKS; ++c) {
        const bool more = (c + 1 < CHUNKS);
        if (more) {
            const int k0 = (c + 1) * 32;
#pragma unroll
            for (int j = 0; j < 4; j++) {
                float4 v = *(const float4*)(Arow + k0 + j * 4);
                a_st[j*4+0]=v.x; a_st[j*4+1]=v.y; a_st[j*4+2]=v.z; a_st[j*4+3]=v.w;
            }
            if (NW == 4) {
                float4 v = *(const float4*)(Wbase + (size_t)k0 * HH);
                w_st[0]=v.x; w_st[1]=v.y; w_st[2]=v.z; w_st[3]=v.w;
            } else {
                float2 v = *(const float2*)(Wbase + (size_t)k0 * HH);
                w_st[0]=v.x; w_st[1]=v.y;
            }
        }
        // compute current chunk
        {
            const float* Ab = As + (kh * 2 + buf) * 32 * 68 + mg * 4;
            const float* Wb = Ws + (kh * 2 + buf) * 32 * WROW + col * (WROW / 8);
#pragma unroll
            for (int kk = 0; kk < 32; ++kk) {
                float4 av = *(const float4*)(Ab + kk * 68);
                ulonglong2 ap = *reinterpret_cast<ulonglong2*>(&av);
                if (BN == 16) {
                    ull w0 = *(const ull*)(Wb + kk * WROW);
                    ull w1 = *(const ull*)(Wb + kk * WROW + 2);
                    fma2(accp[0], ap.x, w0); fma2(accp[1], ap.y, w0);
                    fma2(accp[2], ap.x, w1); fma2(accp[3], ap.y, w1);
                } else {
                    ull w = *(const ull*)(Wb + kk * WROW);
                    fma2(accp[0], ap.x, w); fma2(accp[1], ap.y, w);
                }
            }
        }
        if (more) {
            int asb = (kh * 2 + (buf ^ 1)) * 32 * 68;
            int wsb = (kh * 2 + (buf ^ 1)) * 32 * WROW + wr * WROW;
#pragma unroll
            for (int j = 0; j < 16; j++) As[asb + (akb + j) * 68 + ar] = a_st[j];
#pragma unroll
            for (int j = 0; j < NW; j++) {
                Ws[wsb + (wq + j) * 2 + 0] = w_st[j];
                Ws[wsb + (wq + j) * 2 + 1] = w_st[j];
            }
            __syncthreads();
            buf ^= 1;
        }
    }

    // cross-team reduction: team1 -> Pp, team0 accumulates
    ull* Pq = (ull*)(dyn + AS_FLOATS + 256 * BN);
    __syncthreads();
    if (kh == 1) {
#pragma unroll
        for (int i = 0; i < NA; i++) Pq[t * NA + i] = accp[i];
    }
    __syncthreads();
    if (kh == 0) {
#pragma unroll
        for (int i = 0; i < NA; i++) add2(accp[i], Pq[t * NA + i]);
    }
}

#define SMEM16 ((AS_FLOATS + 256*16 + 128*8) * 4)   // 55296 B
#define SMEM8  ((AS_FLOATS + 256*8  + 128*4) * 4)   // 45056 B

// r0/z0: sigma(X0[g][t] + h0 @ W{r,z}0[E:,:]);  r-branch stores r*h0
__global__ __launch_bounds__(256) void k_gates0(int ts,
    const float* __restrict__ Wr0, const float* __restrict__ Wz0)
{
    const int bn = blockIdx.x * 16;
    const int gate = blockIdx.y;
    const float* W = (gate ? Wz0 : Wr0) + (size_t)EE * HH;
    ull accp[4];
    team_gemm<16, 16>(g_h0, HH, W, bn, accp);
    if (threadIdx.x < 128) {
        const int t = threadIdx.x, mg = t >> 3, col = t & 7;
        float v[4][2];
        unpk(accp[0], v[0][0], v[1][0]); unpk(accp[1], v[2][0], v[3][0]);
        unpk(accp[2], v[0][1], v[1][1]); unpk(accp[3], v[2][1], v[3][1]);
        const float* X = g_X0 + (size_t)gate * SBH + (size_t)ts * BH;
#pragma unroll
        for (int i = 0; i < 4; i++)
#pragma unroll
            for (int j = 0; j < 2; j++) {
                int idx = (mg * 4 + i) * HH + bn + col * 2 + j;
                float s = sigm(v[i][j] + X[idx]);
                if (gate == 0) g_rh0[idx] = s * g_h0[idx];
                else           g_z0[idx] = s;
            }
    }
}

// hh0 = sigma(X0[2][t] + (r*h0) @ Wh0[E:,:]);  h0 <- (1-z)*h0 + z*hh0
__global__ __launch_bounds__(256) void k_cand0(int ts, const float* __restrict__ Wh0)
{
    const int bn = blockIdx.x * 8;
    ull accp[2];
    team_gemm<8, 16>(g_rh0, HH, Wh0 + (size_t)EE * HH, bn, accp);
    if (threadIdx.x < 128) {
        const int t = threadIdx.x, mg = t >> 3, col = t & 7;
        float v[4];
        unpk(accp[0], v[0], v[1]); unpk(accp[1], v[2], v[3]);
        const float* X = g_X0 + 2ull * SBH + (size_t)ts * BH;
#pragma unroll
        for (int i = 0; i < 4; i++) {
            int idx = (mg * 4 + i) * HH + bn + col;
            float hh = sigm(v[i] + X[idx]);
            float h = g_h0[idx], z = g_z0[idx];
            g_h0[idx] = (1.f - z) * h + z * hh;
        }
    }
}

// x1 = sigma(h0 @ Wfc + bfc)
__global__ __launch_bounds__(256) void k_fc(
    const float* __restrict__ Wfc, const float* __restrict__ bfc)
{
    const int bn = blockIdx.x * 8;
    ull accp[2];
    team_gemm<8, 16>(g_h0, HH, Wfc, bn, accp);
    if (threadIdx.x < 128) {
        const int t = threadIdx.x, mg = t >> 3, col = t & 7;
        float v[4];
        unpk(accp[0], v[0], v[1]); unpk(accp[1], v[2], v[3]);
#pragma unroll
        for (int i = 0; i < 4; i++) {
            int b = mg * 4 + i, n = bn + col;
            float x1 = sigm(v[i] + bfc[n]);
            g_cat1[b * 2 * HH + n]  = x1;
            g_cat1h[b * 2 * HH + n] = x1;
        }
    }
}

// r1/z1 = sigma([x1,h1] @ W{r,z}1 + b)
__global__ __launch_bounds__(256) void k_gates1(
    const float* __restrict__ Wr1, const float* __restrict__ Wz1,
    const float* __restrict__ br1, const float* __restrict__ bz1)
{
    const int bn = blockIdx.x * 16;
    const int gate = blockIdx.y;
    const float* W = gate ? Wz1 : Wr1;
    const float* bias = gate ? bz1 : br1;
    ull accp[4];
    team_gemm<16, 32>(g_cat1, 2 * HH, W, bn, accp);
    if (threadIdx.x < 128) {
        const int t = threadIdx.x, mg = t >> 3, col = t & 7;
        float v[4][2];
        unpk(accp[0], v[0][0], v[1][0]); unpk(accp[1], v[2][0], v[3][0]);
        unpk(accp[2], v[0][1], v[1][1]); unpk(accp[3], v[2][1], v[3][1]);
#pragma unroll
        for (int i = 0; i < 4; i++)
#pragma unroll
            for (int j = 0; j < 2; j++) {
                int b = mg * 4 + i, n = bn + col * 2 + j;
                float s = sigm(v[i][j] + bias[n]);
                if (gate == 0) {
                    float h1 = g_cat1[b * 2 * HH + HH + n];
                    g_cat1h[b * 2 * HH + HH + n] = s * h1;
                } else {
                    g_z1[b * HH + n] = s;
                }
            }
    }
}

// hh1 = sigma([x1, r1*h1] @ Wh1 + bh1); h1 update + H1all store
__global__ __launch_bounds__(256) void k_cand1(int ts,
    const float* __restrict__ Wh1, const float* __restrict__ bh1)
{
    const int bn = blockIdx.x * 8;
    ull accp[2];
    team_gemm<8, 32>(g_cat1h, 2 * HH, Wh1, bn, accp);
    if (threadIdx.x < 128) {
        const int t = threadIdx.x, mg = t >> 3, col = t & 7;
        float v[4];
        unpk(accp[0], v[0], v[1]); unpk(accp[1], v[2], v[3]);
#pragma unroll
        for (int i = 0; i < 4; i++) {
            int b = mg * 4 + i, n = bn + col;
            float hh = sigm(v[i] + bh1[n]);
            float h1 = g_cat1[b * 2 * HH + HH + n];
            float z  = g_z1[b * HH + n];
            float hn = (1.f - z) * h1 + z * hh;
            g_cat1[b * 2 * HH + HH + n] = hn;
            g_H1all[(size_t)ts * BH + b * HH + n] = hn;
        }
    }
}

// h_final = [h0, h1] appended after logits
__global__ void k_hfinal(float* __restrict__ out) {
    int i = blockIdx.x * blockDim.x + threadIdx.x;
    if (i < BH) {
        out[i] = g_h0[i];
        int b = i >> 10, n = i & (HH - 1);
        out[BH + i] = g_cat1[b * 2 * HH + HH + n];
    }
}

extern "C" void kernel_launch(void* const* d_in, const int* in_sizes, int n_in,
                              void* d_out, int out_size)
{
    const int*   ids    = (const int*)d_in[0];
    const float* h_init = (const float*)d_in[1];
    const float* emb    = (const float*)d_in[2];
    const float* Wr0 = (const float*)d_in[3],  *Wz0 = (const float*)d_in[4],  *Wh0 = (const float*)d_in[5];
    const float* br0 = (const float*)d_in[6],  *bz0 = (const float*)d_in[7],  *bh0 = (const float*)d_in[8];
    const float* Wr1 = (const float*)d_in[9],  *Wz1 = (const float*)d_in[10], *Wh1 = (const float*)d_in[11];
    const float* br1 = (const float*)d_in[12], *bz1 = (const float*)d_in[13], *bh1 = (const float*)d_in[14];
    const float* Wfc = (const float*)d_in[15], *bfc = (const float*)d_in[16];
    const float* Wout = (const float*)d_in[17], *bout = (const float*)d_in[18];
    float* out = (float*)d_out;

    // allow >48KB dynamic smem for the BN=16 step kernels (host-side, idempotent,
    // not a stream op -> legal under graph capture)
    cudaFuncSetAttribute(k_gates0, cudaFuncAttributeMaxDynamicSharedMemorySize, SMEM16);
    cudaFuncSetAttribute(k_gates1, cudaFuncAttributeMaxDynamicSharedMemorySize, SMEM16);
    cudaFuncSetAttribute(k_cand0,  cudaFuncAttributeMaxDynamicSharedMemorySize, SMEM8);
    cudaFuncSetAttribute(k_fc,     cudaFuncAttributeMaxDynamicSharedMemorySize, SMEM8);
    cudaFuncSetAttribute(k_cand1,  cudaFuncAttributeMaxDynamicSharedMemorySize, SMEM8);

    k_init<<<(BH + 255) / 256, 256>>>(h_init);
    k_embed<<<dim3(HH / 64, (SS * BB) / 64, 3), 256>>>(ids, emb, Wr0, Wz0, Wh0, br0, bz0, bh0);

    for (int t = 0; t < SS; ++t) {
        k_gates0<<<dim3(HH / 16, 2), 256, SMEM16>>>(t, Wr0, Wz0);
        k_cand0<<<HH / 8, 256, SMEM8>>>(t, Wh0);
        k_fc<<<HH / 8, 256, SMEM8>>>(Wfc, bfc);
        k_gates1<<<dim3(HH / 16, 2), 256, SMEM16>>>(Wr1, Wz1, br1, bz1);
        k_cand1<<<HH / 8, 256, SMEM8>>>(t, Wh1, bh1);
    }

    k_out<<<dim3((VV + 63) / 64, (SS * BB) / 64), 256>>>(Wout, bout, out);
    k_hfinal<<<(BH + 255) / 256, 256>>>(out + (size_t)SS * BB * VV);
}

// round 8
// speedup vs baseline: 1.5416x; 1.0538x over previous
#include <cuda_runtime.h>
#include <math.h>

#define VV 10000
#define EE 512
#define HH 1024
#define SS 64
#define BB 64

#define SBH (SS*BB*HH)
#define BH  (BB*HH)

typedef unsigned long long ull;

// ---------------- device scratch ----------------
__device__ float g_X0[3u * SBH];
__device__ float g_H1all[SBH];
__device__ float g_h0[BH];
__device__ float g_rh0[BH];
__device__ float g_z0[BH];
__device__ float g_z1[BH];
__device__ float g_cat1[BB * 2 * HH];   // [x1, h1]
__device__ float g_cat1h[BB * 2 * HH];  // [x1, r1*h1]

__device__ __forceinline__ float sigm(float x) { return 1.0f / (1.0f + __expf(-x)); }

// ---------------- packed f32x2 helpers (sm_103a FFMA2) ----------------
__device__ __forceinline__ void fma2(ull &c, ull a, ull b) {
    asm("fma.rn.f32x2 %0, %1, %2, %0;" : "+l"(c) : "l"(a), "l"(b));
}
__device__ __forceinline__ void add2(ull &c, ull a) {
    asm("add.rn.f32x2 %0, %0, %1;" : "+l"(c) : "l"(a));
}
__device__ __forceinline__ ull pk2(float lo, float hi) {
    ull r; asm("mov.b64 %0, {%1, %2};" : "=l"(r) : "f"(lo), "f"(hi)); return r;
}
__device__ __forceinline__ void unpk(ull v, float &lo, float &hi) {
    asm("mov.b64 {%0, %1}, %2;" : "=f"(lo), "=f"(hi) : "l"(v));
}

// ---------------- init ----------------
__global__ void k_init(const float* __restrict__ h_init) {
    int i = blockIdx.x * blockDim.x + threadIdx.x;
    if (i < BH) {
        g_h0[i] = h_init[i];
        int b = i >> 10, n = i & (HH - 1);
        g_cat1[b * 2 * HH + HH + n] = h_init[BH + i];
    }
}

// ---------------- embedding precompute GEMM (64x64x16, packed fma2) ----------------
__global__ __launch_bounds__(256) void k_embed(
    const int* __restrict__ ids, const float* __restrict__ emb,
    const float* __restrict__ Wr, const float* __restrict__ Wz, const float* __restrict__ Wh,
    const float* __restrict__ br, const float* __restrict__ bz, const float* __restrict__ bh)
{
    const int g = blockIdx.z;
    const float* __restrict__ W    = (g == 0) ? Wr : ((g == 1) ? Wz : Wh);
    const float* __restrict__ bias = (g == 0) ? br : ((g == 1) ? bz : bh);
    float* __restrict__ out = g_X0 + (size_t)g * SBH;

    __shared__ __align__(16) float As[16][68];
    __shared__ __align__(16) float Ws[16][64];
    const int tid = threadIdx.x;
    const int bm = blockIdx.y * 64, bn = blockIdx.x * 64;
    const int lr = tid >> 2, lk = (tid & 3) * 4;
    const int wk = tid >> 4, wn = (tid & 15) * 4;
    const int tx = tid & 15, ty = tid >> 4;
    const float* __restrict__ arow = emb + (size_t)ids[bm + lr] * EE + lk;

    ull accp[4][2];
#pragma unroll
    for (int i = 0; i < 4; i++) { accp[i][0] = 0ull; accp[i][1] = 0ull; }

    for (int k0 = 0; k0 < EE; k0 += 16) {
        float4 av = *(const float4*)(arow + k0);
        As[lk + 0][lr] = av.x; As[lk + 1][lr] = av.y;
        As[lk + 2][lr] = av.z; As[lk + 3][lr] = av.w;
        *(float4*)&Ws[wk][wn] = *(const float4*)(W + (size_t)(k0 + wk) * HH + bn + wn);
        __syncthreads();
#pragma unroll
        for (int kk = 0; kk < 16; kk++) {
            float4 a = *(const float4*)&As[kk][ty * 4];
            float4 w = *(const float4*)&Ws[kk][tx * 4];
            ulonglong2 wp = *reinterpret_cast<ulonglong2*>(&w);
            ull a0 = pk2(a.x, a.x), a1 = pk2(a.y, a.y);
            ull a2 = pk2(a.z, a.z), a3 = pk2(a.w, a.w);
            fma2(accp[0][0], a0, wp.x); fma2(accp[0][1], a0, wp.y);
            fma2(accp[1][0], a1, wp.x); fma2(accp[1][1], a1, wp.y);
            fma2(accp[2][0], a2, wp.x); fma2(accp[2][1], a2, wp.y);
            fma2(accp[3][0], a3, wp.x); fma2(accp[3][1], a3, wp.y);
        }
        __syncthreads();
    }
    float4 bv = *(const float4*)(bias + bn + tx * 4);
#pragma unroll
    for (int i = 0; i < 4; i++) {
        float c0, c1, c2, c3;
        unpk(accp[i][0], c0, c1); unpk(accp[i][1], c2, c3);
        int row = bm + ty * 4 + i;
        float* o = out + (size_t)row * HH + bn + tx * 4;
        o[0] = c0 + bv.x; o[1] = c1 + bv.y; o[2] = c2 + bv.z; o[3] = c3 + bv.w;
    }
}

// ---------------- k_out: logits = H1all @ Wout + bout (packed fma2) ----------------
__global__ __launch_bounds__(256) void k_out(
    const float* __restrict__ Wout, const float* __restrict__ bout,
    float* __restrict__ logits)
{
    __shared__ __align__(16) float As[16][68];
    __shared__ __align__(16) float Ws[16][64];
    const int tid = threadIdx.x;
    const int bm = blockIdx.y * 64, bn = blockIdx.x * 64;
    const int lr = tid >> 2, lk = (tid & 3) * 4;
    const int wk = tid >> 4, wn = (tid & 15) * 4;
    const int tx = tid & 15, ty = tid >> 4;
    const float* __restrict__ arow = g_H1all + (size_t)(bm + lr) * HH + lk;
    const bool wok = (bn + wn + 3) < VV;

    ull accp[4][2];
#pragma unroll
    for (int i = 0; i < 4; i++) { accp[i][0] = 0ull; accp[i][1] = 0ull; }

    for (int k0 = 0; k0 < HH; k0 += 16) {
        float4 av = *(const float4*)(arow + k0);
        As[lk + 0][lr] = av.x; As[lk + 1][lr] = av.y;
        As[lk + 2][lr] = av.z; As[lk + 3][lr] = av.w;
        float4 wv;
        const float* wp = Wout + (size_t)(k0 + wk) * VV;
        if (wok) {
            wv = *(const float4*)(wp + bn + wn);
        } else {
            wv.x = (bn + wn + 0 < VV) ? wp[bn + wn + 0] : 0.f;
            wv.y = (bn + wn + 1 < VV) ? wp[bn + wn + 1] : 0.f;
            wv.z = (bn + wn + 2 < VV) ? wp[bn + wn + 2] : 0.f;
            wv.w = (bn + wn + 3 < VV) ? wp[bn + wn + 3] : 0.f;
        }
        *(float4*)&Ws[wk][wn] = wv;
        __syncthreads();
#pragma unroll
        for (int kk = 0; kk < 16; kk++) {
            float4 a = *(const float4*)&As[kk][ty * 4];
            float4 w = *(const float4*)&Ws[kk][tx * 4];
            ulonglong2 wpk = *reinterpret_cast<ulonglong2*>(&w);
            ull a0 = pk2(a.x, a.x), a1 = pk2(a.y, a.y);
            ull a2 = pk2(a.z, a.z), a3 = pk2(a.w, a.w);
            fma2(accp[0][0], a0, wpk.x); fma2(accp[0][1], a0, wpk.y);
            fma2(accp[1][0], a1, wpk.x); fma2(accp[1][1], a1, wpk.y);
            fma2(accp[2][0], a2, wpk.x); fma2(accp[2][1], a2, wpk.y);
            fma2(accp[3][0], a3, wpk.x); fma2(accp[3][1], a3, wpk.y);
        }
        __syncthreads();
    }
#pragma unroll
    for (int i = 0; i < 4; i++) {
        float c[4];
        unpk(accp[i][0], c[0], c[1]); unpk(accp[i][1], c[2], c[3]);
        int row = bm + ty * 4 + i;
#pragma unroll
        for (int j = 0; j < 4; j++) {
            int col = bn + tx * 4 + j;
            if (col < VV) logits[(size_t)row * VV + col] = c[j] + bout[col];
        }
    }
}

// ================= 1024-thread step GEMM cores =================
// Output tile [64 x 8] per gate; 4-rows x 1-col per thread (128 compute threads);
// packed FFMA2 over row pairs with W duplicated in smem.

// ---- single-gate core: 8 K-teams x 128 threads, BK=16 ----
// smem floats: As 8*2*16*68 = 17408 | Ws 8*2*16*16 = 4096 | Pq 7*128*2 ull
#define SG_SMEM ((17408 + 4096) * 4 + 7*128*2*8)    // 100352 B

template<int KT>
__device__ __forceinline__ void sgemm8(
    const float* __restrict__ A, int lda,
    const float* __restrict__ W, int bn, ull acc[2])
{
    extern __shared__ float dyn[];
    float* As = dyn;
    float* Ws = dyn + 17408;
    ull*   Pq = (ull*)(dyn + 17408 + 4096);

    constexpr int CH = KT / 128;           // chunks per team
    const int tid = threadIdx.x;
    const int team = tid >> 7, t = tid & 127;
    const int koff = team * (KT / 8);
    const int ar = t >> 1, akb = (t & 1) * 8;     // A loader: 64 rows x 16 k
    const int wr = t >> 3, wn = t & 7;            // W loader: 16 rows x 8 cols
    const int mg = t >> 3, col = t & 7;           // compute map

    const float* __restrict__ Arow = A + (size_t)ar * lda + koff + akb;
    const float* __restrict__ Wb   = W + (size_t)(koff + wr) * HH + bn + wn;

    acc[0] = 0ull; acc[1] = 0ull;
    float a_st[8], w_st;

    // prologue: chunk 0
    {
        float4 v0 = *(const float4*)(Arow);
        float4 v1 = *(const float4*)(Arow + 4);
        a_st[0]=v0.x; a_st[1]=v0.y; a_st[2]=v0.z; a_st[3]=v0.w;
        a_st[4]=v1.x; a_st[5]=v1.y; a_st[6]=v1.z; a_st[7]=v1.w;
        w_st = *Wb;
    }
    {
        float* Ab = As + (team * 2) * (16 * 68);
        float* Wd = Ws + (team * 2) * 256;
#pragma unroll
        for (int j = 0; j < 8; j++) Ab[(akb + j) * 68 + ar] = a_st[j];
        Wd[wr * 16 + wn * 2 + 0] = w_st;
        Wd[wr * 16 + wn * 2 + 1] = w_st;
    }
    __syncthreads();

    int buf = 0;
    for (int c = 0; c < CH; ++c) {
        const bool more = (c + 1 < CH);
        if (more) {
            const int k0 = (c + 1) * 16;
            float4 v0 = *(const float4*)(Arow + k0);
            float4 v1 = *(const float4*)(Arow + k0 + 4);
            a_st[0]=v0.x; a_st[1]=v0.y; a_st[2]=v0.z; a_st[3]=v0.w;
            a_st[4]=v1.x; a_st[5]=v1.y; a_st[6]=v1.z; a_st[7]=v1.w;
            w_st = *(Wb + (size_t)k0 * HH);
        }
        {
            const float* Ab = As + (team * 2 + buf) * (16 * 68) + mg * 4;
            const float* Wd = Ws + (team * 2 + buf) * 256 + col * 2;
#pragma unroll
            for (int kk = 0; kk < 16; ++kk) {
                float4 av = *(const float4*)(Ab + kk * 68);
                ulonglong2 ap = *reinterpret_cast<ulonglong2*>(&av);
                ull w = *(const ull*)(Wd + kk * 16);
                fma2(acc[0], ap.x, w); fma2(acc[1], ap.y, w);
            }
        }
        if (more) {
            float* Ab = As + (team * 2 + (buf ^ 1)) * (16 * 68);
            float* Wd = Ws + (team * 2 + (buf ^ 1)) * 256;
#pragma unroll
            for (int j = 0; j < 8; j++) Ab[(akb + j) * 68 + ar] = a_st[j];
            Wd[wr * 16 + wn * 2 + 0] = w_st;
            Wd[wr * 16 + wn * 2 + 1] = w_st;
            __syncthreads();
            buf ^= 1;
        }
    }

    // 8-way reduction: teams 1..7 -> Pq, team0 accumulates
    if (team) { Pq[((team - 1) * 128 + t) * 2 + 0] = acc[0];
                Pq[((team - 1) * 128 + t) * 2 + 1] = acc[1]; }
    __syncthreads();
    if (team == 0) {
#pragma unroll
        for (int r = 0; r < 7; r++) {
            add2(acc[0], Pq[(r * 128 + t) * 2 + 0]);
            add2(acc[1], Pq[(r * 128 + t) * 2 + 1]);
        }
    }
}

// ---- gate-pair core: 4 K-teams x (2 gates x 128 threads), BK=32, shared A tile ----
// smem floats: As 4*2*32*68 = 17408 | Ws 4*2*2*32*16 = 8192 | Pq 3*256*2 ull
#define GG_SMEM ((17408 + 8192) * 4 + 3*256*2*8)    // 114688 B

template<int KT>
__device__ __forceinline__ void ggemm8(
    const float* __restrict__ A, int lda,
    const float* __restrict__ W0, const float* __restrict__ W1,
    int bn, ull acc[2])
{
    extern __shared__ float dyn[];
    float* As = dyn;
    float* Ws = dyn + 17408;
    ull*   Pq = (ull*)(dyn + 17408 + 8192);

    constexpr int CH = KT / 128;
    const int tid = threadIdx.x;
    const int team = tid >> 8, u = tid & 255;
    const int gate = u >> 7, t = u & 127;
    const float* __restrict__ W = gate ? W1 : W0;
    const int koff = team * (KT / 4);
    const int ar = u >> 2, akb = (u & 3) * 8;     // A loader: 256 thr, 64 rows x 32 k
    const int wr = t >> 2, wn = (t & 3) * 2;      // W loader per gate: 32 rows x 8 cols
    const int mg = t >> 3, col = t & 7;

    const float* __restrict__ Arow = A + (size_t)ar * lda + koff + akb;
    const float* __restrict__ Wb   = W + (size_t)(koff + wr) * HH + bn + wn;

    acc[0] = 0ull; acc[1] = 0ull;
    float a_st[8], w0s, w1s;

    // prologue: chunk 0
    {
        float4 v0 = *(const float4*)(Arow);
        float4 v1 = *(const float4*)(Arow + 4);
        a_st[0]=v0.x; a_st[1]=v0.y; a_st[2]=v0.z; a_st[3]=v0.w;
        a_st[4]=v1.x; a_st[5]=v1.y; a_st[6]=v1.z; a_st[7]=v1.w;
        float2 wv = *(const float2*)(Wb);
        w0s = wv.x; w1s = wv.y;
    }
    {
        float* Ab = As + (team * 2) * (32 * 68);
        float* Wd = Ws + ((team * 2) * 2 + gate) * 512;
#pragma unroll
        for (int j = 0; j < 8; j++) Ab[(akb + j) * 68 + ar] = a_st[j];
        Wd[wr * 16 + wn * 2 + 0] = w0s; Wd[wr * 16 + wn * 2 + 1] = w0s;
        Wd[wr * 16 + wn * 2 + 2] = w1s; Wd[wr * 16 + wn * 2 + 3] = w1s;
    }
    __syncthreads();

    int buf = 0;
    for (int c = 0; c < CH; ++c) {
        const bool more = (c + 1 < CH);
        if (more) {
            const int k0 = (c + 1) * 32;
            float4 v0 = *(const float4*)(Arow + k0);
            float4 v1 = *(const float4*)(Arow + k0 + 4);
            a_st[0]=v0.x; a_st[1]=v0.y; a_st[2]=v0.z; a_st[3]=v0.w;
            a_st[4]=v1.x; a_st[5]=v1.y; a_st[6]=v1.z; a_st[7]=v1.w;
            float2 wv = *(const float2*)(Wb + (size_t)k0 * HH);
            w0s = wv.x; w1s = wv.y;
        }
        {
            const float* Ab = As + (team * 2 + buf) * (32 * 68) + mg * 4;
            const float* Wd = Ws + ((team * 2 + buf) * 2 + gate) * 512 + col * 2;
#pragma unroll
            for (int kk = 0; kk < 32; ++kk) {
                float4 av = *(const float4*)(Ab + kk * 68);
                ulonglong2 ap = *reinterpret_cast<ulonglong2*>(&av);
                ull w = *(const ull*)(Wd + kk * 16);
                fma2(acc[0], ap.x, w); fma2(acc[1], ap.y, w);
            }
        }
        if (more) {
            float* Ab = As + (team * 2 + (buf ^ 1)) * (32 * 68);
            float* Wd = Ws + ((team * 2 + (buf ^ 1)) * 2 + gate) * 512;
#pragma unroll
            for (int j = 0; j < 8; j++) Ab[(akb + j) * 68 + ar] = a_st[j];
            Wd[wr * 16 + wn * 2 + 0] = w0s; Wd[wr * 16 + wn * 2 + 1] = w0s;
            Wd[wr * 16 + wn * 2 + 2] = w1s; Wd[wr * 16 + wn * 2 + 3] = w1s;
            __syncthreads();
            buf ^= 1;
        }
    }

    // 4-way reduction: teams 1..3 -> Pq, team0 accumulates
    if (team) { Pq[((team - 1) * 256 + u) * 2 + 0] = acc[0];
                Pq[((team - 1) * 256 + u) * 2 + 1] = acc[1]; }
    __syncthreads();
    if (team == 0) {
#pragma unroll
        for (int r = 0; r < 3; r++) {
            add2(acc[0], Pq[(r * 256 + u) * 2 + 0]);
            add2(acc[1], Pq[(r * 256 + u) * 2 + 1]);
        }
    }
}

// ---------------- step kernels ----------------

// r0 & z0: sigma(X0[g][ts] + h0 @ W{r,z}0[E:,:]); r-branch stores r*h0
__global__ __launch_bounds__(1024, 1) void k_gates0(int ts,
    const float* __restrict__ Wr0, const float* __restrict__ Wz0)
{
    const int bn = blockIdx.x * 8;
    ull acc[2];
    ggemm8<HH>(g_h0, HH, Wr0 + (size_t)EE * HH, Wz0 + (size_t)EE * HH, bn, acc);
    if (threadIdx.x < 256) {
        const int gate = threadIdx.x >> 7, t = threadIdx.x & 127;
        const int mg = t >> 3, col = t & 7;
        float v[4];
        unpk(acc[0], v[0], v[1]); unpk(acc[1], v[2], v[3]);
        const float* X = g_X0 + (size_t)gate * SBH + (size_t)ts * BH;
#pragma unroll
        for (int i = 0; i < 4; i++) {
            int idx = (mg * 4 + i) * HH + bn + col;
            float s = sigm(v[i] + X[idx]);
            if (gate == 0) g_rh0[idx] = s * g_h0[idx];
            else           g_z0[idx] = s;
        }
    }
}

// hh0 = sigma(X0[2][ts] + rh0 @ Wh0[E:,:]); h0 <- (1-z)h + z*hh
__global__ __launch_bounds__(1024, 1) void k_cand0(int ts, const float* __restrict__ Wh0)
{
    const int bn = blockIdx.x * 8;
    ull acc[2];
    sgemm8<HH>(g_rh0, HH, Wh0 + (size_t)EE * HH, bn, acc);
    if (threadIdx.x < 128) {
        const int t = threadIdx.x, mg = t >> 3, col = t & 7;
        float v[4];
        unpk(acc[0], v[0], v[1]); unpk(acc[1], v[2], v[3]);
        const float* X = g_X0 + 2ull * SBH + (size_t)ts * BH;
#pragma unroll
        for (int i = 0; i < 4; i++) {
            int idx = (mg * 4 + i) * HH + bn + col;
            float hh = sigm(v[i] + X[idx]);
            float h = g_h0[idx], z = g_z0[idx];
            g_h0[idx] = (1.f - z) * h + z * hh;
        }
    }
}

// x1 = sigma(h0 @ Wfc + bfc)
__global__ __launch_bounds__(1024, 1) void k_fc(
    const float* __restrict__ Wfc, const float* __restrict__ bfc)
{
    const int bn = blockIdx.x * 8;
    ull acc[2];
    sgemm8<HH>(g_h0, HH, Wfc, bn, acc);
    if (threadIdx.x < 128) {
        const int t = threadIdx.x, mg = t >> 3, col = t & 7;
        float v[4];
        unpk(acc[0], v[0], v[1]); unpk(acc[1], v[2], v[3]);
#pragma unroll
        for (int i = 0; i < 4; i++) {
            int b = mg * 4 + i, n = bn + col;
            float x1 = sigm(v[i] + bfc[n]);
            g_cat1[b * 2 * HH + n]  = x1;
            g_cat1h[b * 2 * HH + n] = x1;
        }
    }
}

// r1 & z1 over [x1, h1] (K=2048)
__global__ __launch_bounds__(1024, 1) void k_gates1(
    const float* __restrict__ Wr1, const float* __restrict__ Wz1,
    const float* __restrict__ br1, const float* __restrict__ bz1)
{
    const int bn = blockIdx.x * 8;
    ull acc[2];
    ggemm8<2 * HH>(g_cat1, 2 * HH, Wr1, Wz1, bn, acc);
    if (threadIdx.x < 256) {
        const int gate = threadIdx.x >> 7, t = threadIdx.x & 127;
        const int mg = t >> 3, col = t & 7;
        float v[4];
        unpk(acc[0], v[0], v[1]); unpk(acc[1], v[2], v[3]);
#pragma unroll
        for (int i = 0; i < 4; i++) {
            int b = mg * 4 + i, n = bn + col;
            if (gate == 0) {
                float s = sigm(v[i] + br1[n]);
                g_cat1h[b * 2 * HH + HH + n] = s * g_cat1[b * 2 * HH + HH + n];
            } else {
                g_z1[b * HH + n] = sigm(v[i] + bz1[n]);
            }
        }
    }
}

// hh1 over [x1, r1*h1] (K=2048); h1 update + H1all store
__global__ __launch_bounds__(1024, 1) void k_cand1(int ts,
    const float* __restrict__ Wh1, const float* __restrict__ bh1)
{
    const int bn = blockIdx.x * 8;
    ull acc[2];
    sgemm8<2 * HH>(g_cat1h, 2 * HH, Wh1, bn, acc);
    if (threadIdx.x < 128) {
        const int t = threadIdx.x, mg = t >> 3, col = t & 7;
        float v[4];
        unpk(acc[0], v[0], v[1]); unpk(acc[1], v[2], v[3]);
#pragma unroll
        for (int i = 0; i < 4; i++) {
            int b = mg * 4 + i, n = bn + col;
            float hh = sigm(v[i] + bh1[n]);
            float h1 = g_cat1[b * 2 * HH + HH + n];
            float z  = g_z1[b * HH + n];
            float hn = (1.f - z) * h1 + z * hh;
            g_cat1[b * 2 * HH + HH + n] = hn;
            g_H1all[(size_t)ts * BH + b * HH + n] = hn;
        }
    }
}

// h_final = [h0, h1] appended after logits
__global__ void k_hfinal(float* __restrict__ out) {
    int i = blockIdx.x * blockDim.x + threadIdx.x;
    if (i < BH) {
        out[i] = g_h0[i];
        int b = i >> 10, n = i & (HH - 1);
        out[BH + i] = g_cat1[b * 2 * HH + HH + n];
    }
}

extern "C" void kernel_launch(void* const* d_in, const int* in_sizes, int n_in,
                              void* d_out, int out_size)
{
    const int*   ids    = (const int*)d_in[0];
    const float* h_init = (const float*)d_in[1];
    const float* emb    = (const float*)d_in[2];
    const float* Wr0 = (const float*)d_in[3],  *Wz0 = (const float*)d_in[4],  *Wh0 = (const float*)d_in[5];
    const float* br0 = (const float*)d_in[6],  *bz0 = (const float*)d_in[7],  *bh0 = (const float*)d_in[8];
    const float* Wr1 = (const float*)d_in[9],  *Wz1 = (const float*)d_in[10], *Wh1 = (const float*)d_in[11];
    const float* br1 = (const float*)d_in[12], *bz1 = (const float*)d_in[13], *bh1 = (const float*)d_in[14];
    const float* Wfc = (const float*)d_in[15], *bfc = (const float*)d_in[16];
    const float* Wout = (const float*)d_in[17], *bout = (const float*)d_in[18];
    float* out = (float*)d_out;

    cudaFuncSetAttribute(k_gates0, cudaFuncAttributeMaxDynamicSharedMemorySize, GG_SMEM);
    cudaFuncSetAttribute(k_gates1, cudaFuncAttributeMaxDynamicSharedMemorySize, GG_SMEM);
    cudaFuncSetAttribute(k_cand0,  cudaFuncAttributeMaxDynamicSharedMemorySize, SG_SMEM);
    cudaFuncSetAttribute(k_fc,     cudaFuncAttributeMaxDynamicSharedMemorySize, SG_SMEM);
    cudaFuncSetAttribute(k_cand1,  cudaFuncAttributeMaxDynamicSharedMemorySize, SG_SMEM);

    k_init<<<(BH + 255) / 256, 256>>>(h_init);
    k_embed<<<dim3(HH / 64, (SS * BB) / 64, 3), 256>>>(ids, emb, Wr0, Wz0, Wh0, br0, bz0, bh0);

    for (int t = 0; t < SS; ++t) {
        k_gates0<<<HH / 8, 1024, GG_SMEM>>>(t, Wr0, Wz0);
        k_cand0<<<HH / 8, 1024, SG_SMEM>>>(t, Wh0);
        k_fc<<<HH / 8, 1024, SG_SMEM>>>(Wfc, bfc);
        k_gates1<<<HH / 8, 1024, GG_SMEM>>>(Wr1, Wz1, br1, bz1);
        k_cand1<<<HH / 8, 1024, SG_SMEM>>>(t, Wh1, bh1);
    }

    k_out<<<dim3((VV + 63) / 64, (SS * BB) / 64), 256>>>(Wout, bout, out);
    k_hfinal<<<(BH + 255) / 256, 256>>>(out + (size_t)SS * BB * VV);
}